// round 1
// baseline (speedup 1.0000x reference)
#include <cuda_runtime.h>

// CompositeValueNoise: out[i] = sum over res in {16,32,64,128} of
//   (16/res) * trilinear-smoothstep interp of V_res at x[i]*res
// x: [N,3] f32, V_res: [(res+1)^3, 4] f32, out: [N,4] f32.

#define N_POINTS 2000000

__device__ __forceinline__ float4 lerp4(const float4 a, const float4 b, const float t) {
    return make_float4(fmaf(t, b.x - a.x, a.x),
                       fmaf(t, b.y - a.y, a.y),
                       fmaf(t, b.z - a.z, a.z),
                       fmaf(t, b.w - a.w, a.w));
}

template <int RES>
__device__ __forceinline__ float4 noise_level(const float4* __restrict__ V,
                                              float px, float py, float pz) {
    const float r = (float)RES;
    float sx = px * r, sy = py * r, sz = pz * r;
    float fx = floorf(sx), fy = floorf(sy), fz = floorf(sz);
    float tx = sx - fx, ty = sy - fy, tz = sz - fz;
    int ix = (int)fx, iy = (int)fy, iz = (int)fz;
    // x in [0,1) guarantees these are in range; clamp defensively (cheap).
    ix = min(ix, RES - 1);
    iy = min(iy, RES - 1);
    iz = min(iz, RES - 1);

    // smoothstep weights (smoothness=2)
    float wx = (3.0f - 2.0f * tx) * tx * tx;
    float wy = (3.0f - 2.0f * ty) * ty * ty;
    float wz = (3.0f - 2.0f * tz) * tz * tz;

    const int S = RES + 1;         // points per axis
    const int SY = S;              // float4 stride for +1 in y
    const int SX = S * S;          // float4 stride for +1 in x
    int base = (ix * S + iy) * S + iz;

    // 8 corners as 4 contiguous 32B pairs (z, z+1) -> one L2 sector each.
    float4 c000 = __ldg(V + base);
    float4 c001 = __ldg(V + base + 1);
    float4 c010 = __ldg(V + base + SY);
    float4 c011 = __ldg(V + base + SY + 1);
    float4 c100 = __ldg(V + base + SX);
    float4 c101 = __ldg(V + base + SX + 1);
    float4 c110 = __ldg(V + base + SX + SY);
    float4 c111 = __ldg(V + base + SX + SY + 1);

    // Interpolate z, then y, then x (order is mathematically equivalent
    // to the reference's x,y,z order).
    float4 az = lerp4(c000, c001, wz);
    float4 bz = lerp4(c010, c011, wz);
    float4 cz = lerp4(c100, c101, wz);
    float4 dz = lerp4(c110, c111, wz);
    float4 ay = lerp4(az, bz, wy);
    float4 by = lerp4(cz, dz, wy);
    return lerp4(ay, by, wx);
}

__global__ void __launch_bounds__(256)
composite_value_noise_kernel(const float* __restrict__ x,
                             const float4* __restrict__ V16,
                             const float4* __restrict__ V32,
                             const float4* __restrict__ V64,
                             const float4* __restrict__ V128,
                             float4* __restrict__ out,
                             int n) {
    int i = blockIdx.x * blockDim.x + threadIdx.x;
    if (i >= n) return;

    float px = x[3 * i + 0];
    float py = x[3 * i + 1];
    float pz = x[3 * i + 2];

    float4 acc = noise_level<16>(V16, px, py, pz);     // mult = 1.0
    float4 t;

    t = noise_level<32>(V32, px, py, pz);              // mult = 0.5
    acc.x = fmaf(0.5f, t.x, acc.x);
    acc.y = fmaf(0.5f, t.y, acc.y);
    acc.z = fmaf(0.5f, t.z, acc.z);
    acc.w = fmaf(0.5f, t.w, acc.w);

    t = noise_level<64>(V64, px, py, pz);              // mult = 0.25
    acc.x = fmaf(0.25f, t.x, acc.x);
    acc.y = fmaf(0.25f, t.y, acc.y);
    acc.z = fmaf(0.25f, t.z, acc.z);
    acc.w = fmaf(0.25f, t.w, acc.w);

    t = noise_level<128>(V128, px, py, pz);            // mult = 0.125
    acc.x = fmaf(0.125f, t.x, acc.x);
    acc.y = fmaf(0.125f, t.y, acc.y);
    acc.z = fmaf(0.125f, t.z, acc.z);
    acc.w = fmaf(0.125f, t.w, acc.w);

    out[i] = acc;
}

extern "C" void kernel_launch(void* const* d_in, const int* in_sizes, int n_in,
                              void* d_out, int out_size) {
    const float*  x    = (const float*)d_in[0];
    const float4* V16  = (const float4*)d_in[1];
    const float4* V32  = (const float4*)d_in[2];
    const float4* V64  = (const float4*)d_in[3];
    const float4* V128 = (const float4*)d_in[4];
    float4* out = (float4*)d_out;

    int n = in_sizes[0] / 3;   // x has N*3 elements
    int threads = 256;
    int blocks = (n + threads - 1) / threads;
    composite_value_noise_kernel<<<blocks, threads>>>(x, V16, V32, V64, V128, out, n);
}